// round 16
// baseline (speedup 1.0000x reference)
#include <cuda_runtime.h>
#include <math_constants.h>

#define BB 8
#define NN 300
#define RR 36
#define CC 256
#define IOU_THR 0.7f
#define CONF_THR 0.3f
#define GG 14            // OUT * SR sample grid per dim
#define NSAMP 196.0f     // 14*14
#define NW 10            // ceil(300/32) live bitmask words
#define NWP 12           // padded to 3 x uint4 per row
#define TMAX (2 * GG * 2 * GG)   // 784 flattened terms max
#define NITEMS (BB * RR * 8)     // pool work items (roi, eighth)
#define POOL_BLOCKS 888          // 6 per SM (48-warp reg cap)

// Scratch (no allocations allowed)
__device__ __align__(16) float4   g_sorted[BB][NN];
__device__ int                    g_nconf[BB];
__device__ __align__(16) unsigned g_adj[BB][NN][NWP];
__device__ float g_sel_boxes[BB * RR * 4];
__device__ int   g_sel_valid[BB * RR];
__device__ int   g_pool_ctr;

// ---------------------------------------------------------------------------
// N1+N2 fused: each block (b, w) redundantly computes the stable sort in its
// own smem (96-way parallel), then its adjacency word. Block w==0 publishes
// sorted boxes + nconf for the greedy kernel, and resets the pool counter.
// ---------------------------------------------------------------------------
__global__ void __launch_bounds__(320)
nms_adj_kernel(const float* __restrict__ boxes,
               const float* __restrict__ scores) {
    __shared__ float sc[NN];
    __shared__ __align__(16) float4 bx4[NN];
    __shared__ float area[NN];
    __shared__ int nconf_sh;

    const int b = blockIdx.x;
    const int w = blockIdx.y;            // 0..NWP-1
    const int t = threadIdx.x;

    if (t == 0) nconf_sh = 0;
    if (b == 0 && w == 0 && t == 1) g_pool_ctr = 0;   // reset work queue
    if (t < NN) sc[t] = scores[b * NN + t];
    __syncthreads();

    // Stable descending rank (ties by original index ascending) + scatter.
    if (t < NN) {
        const float st_ = sc[t];
        const float si = st_ > CONF_THR ? st_ : -CUDART_INF_F;
        int rank = 0;
#pragma unroll 4
        for (int j = 0; j < NN; j++) {
            float sj = sc[j] > CONF_THR ? sc[j] : -CUDART_INF_F;
            rank += (sj > si) || (sj == si && j < t);
        }
        bx4[rank] = ((const float4*)boxes)[b * NN + t];
        if (st_ > CONF_THR) atomicAdd(&nconf_sh, 1);
    }
    __syncthreads();

    if (t < NN) {
        const float4 v = bx4[t];
        area[t] = (v.z - v.x) * (v.w - v.y);
    }
    __syncthreads();
    const int nconf = nconf_sh;

    // Publish sorted boxes + nconf (block w==0 only)
    if (w == 0) {
        if (t < NN) g_sorted[b][t] = bx4[t];
        if (t == 0) g_nconf[b] = nconf;
    }

    // Adjacency word w for all rows i = t.
    const int j0 = w * 32;
    const int jend = min(j0 + 32, nconf);
    if (t < NN) {
        unsigned m = 0;
        if (w < NW && t < nconf) {
            const float4 bi = bx4[t];
            const float ai = area[t];
            for (int j = max(j0, t + 1); j < jend; j++) {
                const float4 bv = bx4[j];
                float lt0 = fmaxf(bi.x, bv.x);
                float lt1 = fmaxf(bi.y, bv.y);
                float rb0 = fminf(bi.z, bv.z);
                float rb1 = fminf(bi.w, bv.w);
                float wd = fmaxf(rb0 - lt0, 0.0f);
                float ht = fmaxf(rb1 - lt1, 0.0f);
                float inter = wd * ht;
                float iou = inter / (ai + area[j] - inter + 1e-9f);
                if (iou > IOU_THR) m |= 1u << (j - j0);
            }
        }
        g_adj[b][t][w] = m;
    }
}

// ---------------------------------------------------------------------------
// N3: bulk-load adjacency into smem, register-resident single-thread greedy,
// parallel popcount-prefix selection. 8 blocks.
// ---------------------------------------------------------------------------
__global__ void __launch_bounds__(512)
nms_greedy_kernel() {
    __shared__ __align__(16) unsigned adj[NN][NWP];
    __shared__ __align__(16) float4 bx4[NN];
    __shared__ unsigned fin[NW];

    const int b = blockIdx.x;
    const int t = threadIdx.x;
    const int nconf = g_nconf[b];

    for (int idx = t; idx < NN * NWP / 4; idx += 512)
        ((uint4*)adj)[idx] = ((const uint4*)g_adj[b])[idx];
    for (int idx = t; idx < NN; idx += 512)
        bx4[idx] = g_sorted[b][idx];
    __syncthreads();

    if (t == 0) {
        const int nwc = (nconf + 31) >> 5;
        unsigned kw[NWP];
#pragma unroll
        for (int w = 0; w < NWP; w++) {
            int lo = w * 32;
            if (lo >= nconf) kw[w] = 0u;
            else if (lo + 32 <= nconf) kw[w] = 0xffffffffu;
            else kw[w] = (1u << (nconf - lo)) - 1u;
        }
        for (int wo = 0; wo < nwc; wo++) {
            unsigned rem = kw[wo];
            while (rem) {
                const int bit = __ffs(rem) - 1;
                const int i = wo * 32 + bit;
                const uint4* row = (const uint4*)&adj[i][0];
                uint4 r0 = row[0], r1 = row[1], r2 = row[2];
                kw[0] &= ~r0.x;  kw[1] &= ~r0.y;  kw[2]  &= ~r0.z;  kw[3]  &= ~r0.w;
                kw[4] &= ~r1.x;  kw[5] &= ~r1.y;  kw[6]  &= ~r1.z;  kw[7]  &= ~r1.w;
                kw[8] &= ~r2.x;  kw[9] &= ~r2.y;  kw[10] &= ~r2.z;  kw[11] &= ~r2.w;
                rem &= ~(1u << bit);
                rem &= kw[wo];           // adj holds only j>i bits — safe
            }
        }
#pragma unroll
        for (int w = 0; w < NW; w++) fin[w] = kw[w];
    }
    __syncthreads();

    if (t < NN) {
        const int wo = t >> 5, bit = t & 31;
        if ((fin[wo] >> bit) & 1u) {
            int pre = __popc(fin[wo] & (bit ? ((1u << bit) - 1u) : 0u));
            for (int w = 0; w < wo; w++) pre += __popc(fin[w]);
            if (pre < RR) {
                const float4 v = bx4[t];
                float* dst = g_sel_boxes + (size_t)(b * RR + pre) * 4;
                dst[0] = v.x; dst[1] = v.y; dst[2] = v.z; dst[3] = v.w;
                g_sel_valid[b * RR + pre] = 1;
            }
        }
    }
    if (t < RR) {
        int K = 0;
        for (int w = 0; w < NW; w++) K += __popc(fin[w]);
        if (t >= K) {
            float* dst = g_sel_boxes + (size_t)(b * RR + t) * 4;
            dst[0] = dst[1] = dst[2] = dst[3] = 0.0f;
            g_sel_valid[b * RR + t] = 0;
        }
    }
}

// ---------------------------------------------------------------------------
// Pool: PERSISTENT blocks + atomic work queue over (roi, eighth) items.
// Flattened term list wf/of in smem; 8 warps x 4 channels (spaced 8).
// ---------------------------------------------------------------------------
__global__ void __launch_bounds__(256)
pool_kernel(const float* __restrict__ f0,
            const float* __restrict__ f1,
            const float* __restrict__ f2,
            const float* __restrict__ f3,
            float* __restrict__ out) {
    const int tid  = threadIdx.x;
    const int w    = tid >> 5;          // warp 0..7
    const int lane = tid & 31;

    __shared__ int item_sh;
    __shared__ float tWy[2 * GG], tWx[2 * GG];
    __shared__ int   tIy[2 * GG], tIx[2 * GG];
    __shared__ float cWy[2 * GG], cWx[2 * GG];
    __shared__ int   cOy[2 * GG], cIx[2 * GG];
    __shared__ int   cnt[2];
    __shared__ float wf[TMAX];
    __shared__ int   of[TMAX];

    while (true) {
        if (tid == 0) item_sh = atomicAdd(&g_pool_ctr, 1);
        __syncthreads();
        const int item = item_sh;
        if (item >= NITEMS) break;

        const int br = item >> 3;       // b*R + r
        const int e  = item & 7;        // channel eighth
        const int b  = br / RR;

        if (!g_sel_valid[br]) {
            if (tid < 32) out[(size_t)br * CC + e * 32 + tid] = 0.0f;
            __syncthreads();
            continue;
        }

        const float x1 = g_sel_boxes[(size_t)br * 4 + 0];
        const float y1 = g_sel_boxes[(size_t)br * 4 + 1];
        const float x2 = g_sel_boxes[(size_t)br * 4 + 2];
        const float y2 = g_sel_boxes[(size_t)br * 4 + 3];

        const float dx = x2 - x1, dy = y2 - y1;
        const float size = sqrtf(fmaxf(dx * dx + dy * dy, 1e-12f));
        const float lvf = floorf(4.0f + log2f(size * (4.0f / 224.0f)));
        const int lv = (int)(fminf(fmaxf(lvf, 2.0f), 5.0f)) - 2;

        const int H = 200 >> lv;        // 200, 100, 50, 25
        const int HH = H * H;
        const float Hf = (float)H;
        const float* F = (lv == 0) ? f0 : (lv == 1) ? f1 : (lv == 2) ? f2 : f3;

        const float rw = fmaxf(dx, 1.0f);
        const float rh = fmaxf(dy, 1.0f);

        if (tid < GG) {
            const float Yv = y1 + rh * ((tid + 0.5f) / (float)GG);
            const bool oob = (Yv < -1.0f) || (Yv > Hf);
            const float yc = fminf(fmaxf(Yv, 0.0f), Hf - 1.0f);
            const int y0 = (int)floorf(yc);
            const int yi1 = min(y0 + 1, H - 1);
            const float ly = yc - (float)y0;
            tIy[2 * tid]     = y0;  tWy[2 * tid]     = oob ? 0.0f : (1.0f - ly);
            tIy[2 * tid + 1] = yi1; tWy[2 * tid + 1] = oob ? 0.0f : ly;
        } else if (tid >= 32 && tid < 32 + GG) {
            const int a = tid - 32;
            const float Xv = x1 + rw * ((a + 0.5f) / (float)GG);
            const bool oob = (Xv < -1.0f) || (Xv > Hf);
            const float xc = fminf(fmaxf(Xv, 0.0f), Hf - 1.0f);
            const int x0 = (int)floorf(xc);
            const int xi1 = min(x0 + 1, H - 1);
            const float lx = xc - (float)x0;
            tIx[2 * a]     = x0;  tWx[2 * a]     = oob ? 0.0f : (1.0f - lx);
            tIx[2 * a + 1] = xi1; tWx[2 * a + 1] = oob ? 0.0f : lx;
        }
        __syncthreads();

        if (tid == 0) {
            int n = 0;
            for (int i = 0; i < 2 * GG; i++)
                if (tWy[i] != 0.0f) { cWy[n] = tWy[i]; cOy[n] = tIy[i] * H; n++; }
            cnt[0] = n;
        }
        if (tid == 32) {
            int n = 0;
            for (int i = 0; i < 2 * GG; i++)
                if (tWx[i] != 0.0f) { cWx[n] = tWx[i]; cIx[n] = tIx[i]; n++; }
            cnt[1] = n;
        }
        __syncthreads();

        const int ny = cnt[0], nx = cnt[1];
        const int T = ny * nx;

        for (int t = tid; t < T; t += 256) {
            const int i = t / nx;
            const int j = t - i * nx;
            wf[t] = cWy[i] * cWx[j];
            of[t] = cOy[i] + cIx[j];
        }
        __syncthreads();

        float a0 = 0.0f, a1 = 0.0f, a2 = 0.0f, a3 = 0.0f;
        {
            const float* F0 = F + (size_t)(b * CC + e * 32 + w) * HH;
            const float* F1 = F0 + (size_t)8  * HH;
            const float* F2 = F0 + (size_t)16 * HH;
            const float* F3 = F0 + (size_t)24 * HH;
            int t = lane;
            for (; t + 32 < T; t += 64) {
                const float w0 = wf[t];       const int o0 = of[t];
                const float w1 = wf[t + 32];  const int o1 = of[t + 32];
                a0 += w0 * __ldg(F0 + o0) + w1 * __ldg(F0 + o1);
                a1 += w0 * __ldg(F1 + o0) + w1 * __ldg(F1 + o1);
                a2 += w0 * __ldg(F2 + o0) + w1 * __ldg(F2 + o1);
                a3 += w0 * __ldg(F3 + o0) + w1 * __ldg(F3 + o1);
            }
            if (t < T) {
                const float w0 = wf[t];  const int o0 = of[t];
                a0 += w0 * __ldg(F0 + o0);
                a1 += w0 * __ldg(F1 + o0);
                a2 += w0 * __ldg(F2 + o0);
                a3 += w0 * __ldg(F3 + o0);
            }
        }
#pragma unroll
        for (int o = 16; o; o >>= 1) {
            a0 += __shfl_xor_sync(0xffffffffu, a0, o);
            a1 += __shfl_xor_sync(0xffffffffu, a1, o);
            a2 += __shfl_xor_sync(0xffffffffu, a2, o);
            a3 += __shfl_xor_sync(0xffffffffu, a3, o);
        }
        if (lane == 0) {
            float* ob = out + (size_t)br * CC + e * 32 + w;
            ob[0]  = a0 * (1.0f / NSAMP);
            ob[8]  = a1 * (1.0f / NSAMP);
            ob[16] = a2 * (1.0f / NSAMP);
            ob[24] = a3 * (1.0f / NSAMP);
        }
        __syncthreads();   // smem tables reused next item
    }
}

// ---------------------------------------------------------------------------
extern "C" void kernel_launch(void* const* d_in, const int* in_sizes, int n_in,
                              void* d_out, int out_size) {
    const float* boxes  = (const float*)d_in[0];   // (B, N, 4)
    const float* scores = (const float*)d_in[1];   // (B, N)
    const float* feat0  = (const float*)d_in[2];   // (B, C, 200, 200)
    const float* feat1  = (const float*)d_in[3];   // (B, C, 100, 100)
    const float* feat2  = (const float*)d_in[4];   // (B, C, 50, 50)
    const float* feat3  = (const float*)d_in[5];   // (B, C, 25, 25)
    float* out = (float*)d_out;                    // (B, R, C)

    nms_adj_kernel<<<dim3(BB, NWP), 320>>>(boxes, scores);
    nms_greedy_kernel<<<BB, 512>>>();
    pool_kernel<<<POOL_BLOCKS, 256>>>(feat0, feat1, feat2, feat3, out);
}

// round 17
// speedup vs baseline: 1.0791x; 1.0791x over previous
#include <cuda_runtime.h>
#include <math_constants.h>

#define BB 8
#define NN 300
#define RR 36
#define CC 256
#define IOU_THR 0.7f
#define CONF_THR 0.3f
#define GG 14            // OUT * SR sample grid per dim
#define NSAMP 196.0f     // 14*14
#define NW 10            // ceil(300/32) live bitmask words
#define NWP 12           // padded to 3 x uint4 per row
#define TMAX (2 * GG * 2 * GG)   // 784 flattened terms max
#define NITEMS (BB * RR * 8)     // pool work items (roi, eighth)
#define POOL_BLOCKS 888          // ~6 per SM

// Scratch (no allocations allowed)
__device__ __align__(16) float4   g_sorted[BB][NN];
__device__ float                  g_area[BB][NN];
__device__ int                    g_nconf[BB];
__device__ __align__(16) unsigned g_adj[BB][NN][NWP];
__device__ float g_sel_boxes[BB * RR * 4];
__device__ int   g_sel_valid[BB * RR];
__device__ int   g_pool_ctr;

// ---------------------------------------------------------------------------
// N1: stable descending rank (3-way chunked partial ranks + shared atomics),
// scatter sorted boxes + areas + nconf to global scratch. 8 blocks.
// Also resets the pool work-queue counter (runs before pool every replay).
// ---------------------------------------------------------------------------
__global__ void __launch_bounds__(1024)
nms_rank_kernel(const float* __restrict__ boxes,
                const float* __restrict__ scores) {
    __shared__ float sc[NN];
    __shared__ int rankq[NN];
    __shared__ int nconf_sh;

    const int b = blockIdx.x;
    const int t = threadIdx.x;

    if (t == 0) nconf_sh = 0;
    if (b == 0 && t == 1) g_pool_ctr = 0;
    if (t < NN) { sc[t] = scores[b * NN + t]; rankq[t] = 0; }
    __syncthreads();

    if (t < 3 * NN) {
        const int i = t % NN;
        const int k = t / NN;            // 0..2
        const float si0 = sc[i];
        const float si = si0 > CONF_THR ? si0 : -CUDART_INF_F;
        const int j0 = k * 100, j1 = j0 + 100;
        int r = 0;
#pragma unroll 4
        for (int j = j0; j < j1; j++) {
            float sj = sc[j] > CONF_THR ? sc[j] : -CUDART_INF_F;
            r += (sj > si) || (sj == si && j < i);
        }
        if (r) atomicAdd(&rankq[i], r);
    }
    if (t < NN && sc[t] > CONF_THR) atomicAdd(&nconf_sh, 1);
    __syncthreads();

    if (t < NN) {
        const float4 v = ((const float4*)boxes)[b * NN + t];
        const int r = rankq[t];
        g_sorted[b][r] = v;
        g_area[b][r] = (v.z - v.x) * (v.w - v.y);
    }
    if (t == 0) g_nconf[b] = nconf_sh;
}

// ---------------------------------------------------------------------------
// N2: adjacency word w (32 j's) for all rows i. Grid (8, 12) — 96 blocks.
// ---------------------------------------------------------------------------
__global__ void __launch_bounds__(320)
nms_adj_kernel() {
    const int b = blockIdx.x;
    const int w = blockIdx.y;            // 0..NWP-1
    const int t = threadIdx.x;

    __shared__ float4 bj[32];
    __shared__ float  aj[32];

    const int nconf = g_nconf[b];
    const int j0 = w * 32;
    const int jend = min(j0 + 32, nconf);

    if (t < 32) {
        const int j = j0 + t;
        if (j < jend) { bj[t] = g_sorted[b][j]; aj[t] = g_area[b][j]; }
    }
    __syncthreads();

    if (t < NN) {
        unsigned m = 0;
        if (w < NW && t < nconf) {
            const float4 bi = g_sorted[b][t];
            const float ai = g_area[b][t];
            for (int j = max(j0, t + 1); j < jend; j++) {
                const float4 bv = bj[j - j0];
                float lt0 = fmaxf(bi.x, bv.x);
                float lt1 = fmaxf(bi.y, bv.y);
                float rb0 = fminf(bi.z, bv.z);
                float rb1 = fminf(bi.w, bv.w);
                float wd = fmaxf(rb0 - lt0, 0.0f);
                float ht = fmaxf(rb1 - lt1, 0.0f);
                float inter = wd * ht;
                float iou = inter / (ai + aj[j - j0] - inter + 1e-9f);
                if (iou > IOU_THR) m |= 1u << (j - j0);
            }
        }
        g_adj[b][t][w] = m;
    }
}

// ---------------------------------------------------------------------------
// N3: bulk-load adjacency into smem, register-resident single-thread greedy,
// parallel popcount-prefix selection. 8 blocks.
// ---------------------------------------------------------------------------
__global__ void __launch_bounds__(512)
nms_greedy_kernel() {
    __shared__ __align__(16) unsigned adj[NN][NWP];
    __shared__ __align__(16) float4 bx4[NN];
    __shared__ unsigned fin[NW];

    const int b = blockIdx.x;
    const int t = threadIdx.x;
    const int nconf = g_nconf[b];

    for (int idx = t; idx < NN * NWP / 4; idx += 512)
        ((uint4*)adj)[idx] = ((const uint4*)g_adj[b])[idx];
    for (int idx = t; idx < NN; idx += 512)
        bx4[idx] = g_sorted[b][idx];
    __syncthreads();

    if (t == 0) {
        const int nwc = (nconf + 31) >> 5;
        unsigned kw[NWP];
#pragma unroll
        for (int w = 0; w < NWP; w++) {
            int lo = w * 32;
            if (lo >= nconf) kw[w] = 0u;
            else if (lo + 32 <= nconf) kw[w] = 0xffffffffu;
            else kw[w] = (1u << (nconf - lo)) - 1u;
        }
        for (int wo = 0; wo < nwc; wo++) {
            unsigned rem = kw[wo];
            while (rem) {
                const int bit = __ffs(rem) - 1;
                const int i = wo * 32 + bit;
                const uint4* row = (const uint4*)&adj[i][0];
                uint4 r0 = row[0], r1 = row[1], r2 = row[2];
                kw[0] &= ~r0.x;  kw[1] &= ~r0.y;  kw[2]  &= ~r0.z;  kw[3]  &= ~r0.w;
                kw[4] &= ~r1.x;  kw[5] &= ~r1.y;  kw[6]  &= ~r1.z;  kw[7]  &= ~r1.w;
                kw[8] &= ~r2.x;  kw[9] &= ~r2.y;  kw[10] &= ~r2.z;  kw[11] &= ~r2.w;
                rem &= ~(1u << bit);
                rem &= kw[wo];           // adj holds only j>i bits — safe
            }
        }
#pragma unroll
        for (int w = 0; w < NW; w++) fin[w] = kw[w];
    }
    __syncthreads();

    if (t < NN) {
        const int wo = t >> 5, bit = t & 31;
        if ((fin[wo] >> bit) & 1u) {
            int pre = __popc(fin[wo] & (bit ? ((1u << bit) - 1u) : 0u));
            for (int w = 0; w < wo; w++) pre += __popc(fin[w]);
            if (pre < RR) {
                const float4 v = bx4[t];
                float* dst = g_sel_boxes + (size_t)(b * RR + pre) * 4;
                dst[0] = v.x; dst[1] = v.y; dst[2] = v.z; dst[3] = v.w;
                g_sel_valid[b * RR + pre] = 1;
            }
        }
    }
    if (t < RR) {
        int K = 0;
        for (int w = 0; w < NW; w++) K += __popc(fin[w]);
        if (t >= K) {
            float* dst = g_sel_boxes + (size_t)(b * RR + t) * 4;
            dst[0] = dst[1] = dst[2] = dst[3] = 0.0f;
            g_sel_valid[b * RR + t] = 0;
        }
    }
}

// ---------------------------------------------------------------------------
// Pool: PERSISTENT blocks + atomic work queue over (roi, eighth) items.
// Warp-ballot prefix compaction of the per-axis tables (no serial loops);
// flattened term list wf/of in smem; 8 warps x 4 channels (spaced 8).
// ---------------------------------------------------------------------------
__global__ void __launch_bounds__(256)
pool_kernel(const float* __restrict__ f0,
            const float* __restrict__ f1,
            const float* __restrict__ f2,
            const float* __restrict__ f3,
            float* __restrict__ out) {
    const int tid  = threadIdx.x;
    const int w    = tid >> 5;          // warp 0..7
    const int lane = tid & 31;

    __shared__ int item_sh;
    __shared__ float cWy[2 * GG], cWx[2 * GG];
    __shared__ int   cOy[2 * GG], cIx[2 * GG];
    __shared__ int   cnt[2];
    __shared__ float wf[TMAX];
    __shared__ int   of[TMAX];

    while (true) {
        if (tid == 0) item_sh = atomicAdd(&g_pool_ctr, 1);
        __syncthreads();
        const int item = item_sh;
        if (item >= NITEMS) break;

        const int br = item >> 3;       // b*R + r
        const int e  = item & 7;        // channel eighth
        const int b  = br / RR;

        if (!g_sel_valid[br]) {
            if (tid < 32) out[(size_t)br * CC + e * 32 + tid] = 0.0f;
            __syncthreads();
            continue;
        }

        const float x1 = g_sel_boxes[(size_t)br * 4 + 0];
        const float y1 = g_sel_boxes[(size_t)br * 4 + 1];
        const float x2 = g_sel_boxes[(size_t)br * 4 + 2];
        const float y2 = g_sel_boxes[(size_t)br * 4 + 3];

        const float dx = x2 - x1, dy = y2 - y1;
        const float size = sqrtf(fmaxf(dx * dx + dy * dy, 1e-12f));
        const float lvf = floorf(4.0f + log2f(size * (4.0f / 224.0f)));
        const int lv = (int)(fminf(fmaxf(lvf, 2.0f), 5.0f)) - 2;

        const int H = 200 >> lv;        // 200, 100, 50, 25
        const int HH = H * H;
        const float Hf = (float)H;
        const float* F = (lv == 0) ? f0 : (lv == 1) ? f1 : (lv == 2) ? f2 : f3;

        const float rw = fmaxf(dx, 1.0f);
        const float rh = fmaxf(dy, 1.0f);

        // Warp 0: y-axis table; warp 1: x-axis table. Entry = lane (0..27):
        // g = lane>>1 grid sample, p = lane&1 selects (floor, frac) pair.
        // Ballot-prefix compaction preserves order.
        if (w < 2) {
            const int g = lane >> 1, p = lane & 1;
            float wt = 0.0f; int idx = 0;
            if (lane < 2 * GG) {
                const float base = (w == 0) ? y1 : x1;
                const float ext  = (w == 0) ? rh : rw;
                const float V = base + ext * ((g + 0.5f) / (float)GG);
                const bool oob = (V < -1.0f) || (V > Hf);
                const float vc = fminf(fmaxf(V, 0.0f), Hf - 1.0f);
                const int v0 = (int)floorf(vc);
                const int v1i = min(v0 + 1, H - 1);
                const float lf = vc - (float)v0;
                wt = oob ? 0.0f : (p ? lf : 1.0f - lf);
                idx = p ? v1i : v0;
            }
            const unsigned mask = __ballot_sync(0xffffffffu, wt != 0.0f);
            if (wt != 0.0f) {
                const int pos = __popc(mask & ((1u << lane) - 1u));
                if (w == 0) { cWy[pos] = wt; cOy[pos] = idx * H; }
                else        { cWx[pos] = wt; cIx[pos] = idx; }
            }
            if (lane == 0) cnt[w] = __popc(mask);
        }
        __syncthreads();

        const int ny = cnt[0], nx = cnt[1];
        const int T = ny * nx;

        for (int t = tid; t < T; t += 256) {
            const int i = t / nx;
            const int j = t - i * nx;
            wf[t] = cWy[i] * cWx[j];
            of[t] = cOy[i] + cIx[j];
        }
        __syncthreads();

        float a0 = 0.0f, a1 = 0.0f, a2 = 0.0f, a3 = 0.0f;
        {
            const float* F0 = F + (size_t)(b * CC + e * 32 + w) * HH;
            const float* F1 = F0 + (size_t)8  * HH;
            const float* F2 = F0 + (size_t)16 * HH;
            const float* F3 = F0 + (size_t)24 * HH;
            int t = lane;
            for (; t + 32 < T; t += 64) {
                const float w0 = wf[t];       const int o0 = of[t];
                const float w1 = wf[t + 32];  const int o1 = of[t + 32];
                a0 += w0 * __ldg(F0 + o0) + w1 * __ldg(F0 + o1);
                a1 += w0 * __ldg(F1 + o0) + w1 * __ldg(F1 + o1);
                a2 += w0 * __ldg(F2 + o0) + w1 * __ldg(F2 + o1);
                a3 += w0 * __ldg(F3 + o0) + w1 * __ldg(F3 + o1);
            }
            if (t < T) {
                const float w0 = wf[t];  const int o0 = of[t];
                a0 += w0 * __ldg(F0 + o0);
                a1 += w0 * __ldg(F1 + o0);
                a2 += w0 * __ldg(F2 + o0);
                a3 += w0 * __ldg(F3 + o0);
            }
        }
#pragma unroll
        for (int o = 16; o; o >>= 1) {
            a0 += __shfl_xor_sync(0xffffffffu, a0, o);
            a1 += __shfl_xor_sync(0xffffffffu, a1, o);
            a2 += __shfl_xor_sync(0xffffffffu, a2, o);
            a3 += __shfl_xor_sync(0xffffffffu, a3, o);
        }
        if (lane == 0) {
            float* ob = out + (size_t)br * CC + e * 32 + w;
            ob[0]  = a0 * (1.0f / NSAMP);
            ob[8]  = a1 * (1.0f / NSAMP);
            ob[16] = a2 * (1.0f / NSAMP);
            ob[24] = a3 * (1.0f / NSAMP);
        }
        __syncthreads();   // smem tables reused next item
    }
}

// ---------------------------------------------------------------------------
extern "C" void kernel_launch(void* const* d_in, const int* in_sizes, int n_in,
                              void* d_out, int out_size) {
    const float* boxes  = (const float*)d_in[0];   // (B, N, 4)
    const float* scores = (const float*)d_in[1];   // (B, N)
    const float* feat0  = (const float*)d_in[2];   // (B, C, 200, 200)
    const float* feat1  = (const float*)d_in[3];   // (B, C, 100, 100)
    const float* feat2  = (const float*)d_in[4];   // (B, C, 50, 50)
    const float* feat3  = (const float*)d_in[5];   // (B, C, 25, 25)
    float* out = (float*)d_out;                    // (B, R, C)

    nms_rank_kernel<<<BB, 1024>>>(boxes, scores);
    nms_adj_kernel<<<dim3(BB, NWP), 320>>>();
    nms_greedy_kernel<<<BB, 512>>>();
    pool_kernel<<<POOL_BLOCKS, 256>>>(feat0, feat1, feat2, feat3, out);
}